// round 5
// baseline (speedup 1.0000x reference)
#include <cuda_runtime.h>

#define BB 8
#define DD 4096
#define HH 32
#define HDD 128
#define KVV 512
#define PASTN 8191
#define TOTALN 8192
#define SCALEF 0.08838834764831845f  // 128^-0.5
#define NSC 16   // s-splits for attention
#define NKC 16   // k-splits for qabs

// ---------------- scratch ----------------
__device__ float g_cnew[BB * KVV];
__device__ float g_qpart[NKC * BB * HH * KVV];
__device__ float g_qabs[BB * HH * KVV];
__device__ float g_opart[NSC * BB * HH * KVV];
__device__ float g_ml[NSC * BB * HH * 2];
__device__ float g_oc[BB * HH * KVV];
__device__ float g_ohead[BB * HH * HDD];

// packed dual-fp32 FMA (sm_100+)
__device__ __forceinline__ float2 ffma2(const float2 a, const float2 b, const float2 c) {
    float2 d;
    asm("fma.rn.f32x2 %0, %1, %2, %3;"
        : "=l"(*(unsigned long long*)&d)
        : "l"(*(const unsigned long long*)&a),
          "l"(*(const unsigned long long*)&b),
          "l"(*(const unsigned long long*)&c));
    return d;
}

__device__ __forceinline__ void cp_async16(unsigned s, const void* g) {
    asm volatile("cp.async.cg.shared.global [%0], [%1], 16;" :: "r"(s), "l"(g));
}
__device__ __forceinline__ void cp_commit() {
    asm volatile("cp.async.commit_group;");
}

// ---------------- K0: zero d_out, g_cnew, g_ohead ----------------
__global__ void k_init(float* __restrict__ out) {
    int i = blockIdx.x * 256 + threadIdx.x;       // 32768
    out[i] = 0.f;
    g_ohead[i] = 0.f;
    if (i < BB * KVV) g_cnew[i] = 0.f;
}

// ---------------- K1: c_new = x @ w_compress (k-split, atomic) ----------------
__global__ __launch_bounds__(256) void k_compress(const float* __restrict__ x,
                                                  const float* __restrict__ wc) {
    __shared__ float2 xd[128][8];   // [k][b] dup pairs
    int kc = blockIdx.x;            // 32 chunks of 128 k
    int tid = threadIdx.x;
    for (int i = tid; i < 1024; i += 256) {
        int k = i >> 3, b = i & 7;
        float v = x[b * DD + kc * 128 + k];
        xd[k][b] = make_float2(v, v);
    }
    __syncthreads();
    float2 acc[BB];
    #pragma unroll
    for (int b = 0; b < BB; b++) acc[b] = make_float2(0.f, 0.f);
    const float* wp = wc + (size_t)kc * 128 * KVV + tid * 2;
    #pragma unroll 8
    for (int k = 0; k < 128; k++) {
        float2 w2 = *(const float2*)(wp + (size_t)k * KVV);
        #pragma unroll
        for (int b = 0; b < BB; b++)
            acc[b] = ffma2(xd[k][b], w2, acc[b]);
    }
    #pragma unroll
    for (int b = 0; b < BB; b++) {
        atomicAdd(&g_cnew[b * KVV + tid * 2 + 0], acc[b].x);
        atomicAdd(&g_cnew[b * KVV + tid * 2 + 1], acc[b].y);
    }
}

// ---------------- K2: q_abs partials (scale folded into x) ----------------
// grid (kc=16, h=32); 128 threads; thread owns n-quad tid*4
__global__ __launch_bounds__(128) void k_qabs(const float* __restrict__ x,
                                              const float* __restrict__ aqk) {
    __shared__ float2 xd[256][8];   // [k][b] dup pairs, pre-scaled (16KB)
    int kc = blockIdx.x;
    int h  = blockIdx.y;
    int tid = threadIdx.x;
    for (int i = tid; i < 2048; i += 128) {
        int k = i >> 3, b = i & 7;
        float v = x[b * DD + kc * 256 + k] * SCALEF;
        xd[k][b] = make_float2(v, v);
    }
    __syncthreads();
    float2 acc[BB][2];
    #pragma unroll
    for (int b = 0; b < BB; b++) {
        acc[b][0] = make_float2(0.f, 0.f);
        acc[b][1] = make_float2(0.f, 0.f);
    }
    const float* ap = aqk + ((size_t)h * DD + (size_t)kc * 256) * KVV + tid * 4;
    #pragma unroll 8
    for (int k = 0; k < 256; k++) {
        float4 a4 = *(const float4*)(ap + (size_t)k * KVV);
        float2 alo = make_float2(a4.x, a4.y);
        float2 ahi = make_float2(a4.z, a4.w);
        #pragma unroll
        for (int b = 0; b < BB; b++) {
            float2 xb = xd[k][b];
            acc[b][0] = ffma2(alo, xb, acc[b][0]);
            acc[b][1] = ffma2(ahi, xb, acc[b][1]);
        }
    }
    #pragma unroll
    for (int b = 0; b < BB; b++) {
        float4 r = make_float4(acc[b][0].x, acc[b][0].y, acc[b][1].x, acc[b][1].y);
        *(float4*)&g_qpart[((size_t)(kc * BB + b) * HH + h) * KVV + tid * 4] = r;
    }
}

// reduce NKC k-partials -> g_qabs
__global__ void k_redq() {
    int i = blockIdx.x * 256 + threadIdx.x;   // 32768 float4 columns
    const float4* p = (const float4*)g_qpart;
    float4 s = make_float4(0.f, 0.f, 0.f, 0.f);
    #pragma unroll
    for (int c = 0; c < NKC; c++) {
        float4 t = p[c * 32768 + i];
        s.x += t.x; s.y += t.y; s.z += t.z; s.w += t.w;
    }
    ((float4*)g_qabs)[i] = s;
}

// ---------------- K3: fused attention (split-KV flash decode) ----------------
// grid (sc=16, b=8); 256 threads; smem:
//   sc_s [32h][521]                          16672 fl   (scores, stride 521 conflict-free)
//   union:
//     phase A: cbA0/cbA1 [64n][130s] (8320 ea), qbA0/qbA1 float2[64][32] (4096 fl ea)
//     phase B: cbB 2x[32s][512n] (16384 ea), ad float2[32s][32h] (2048 fl)
#define SC_STRIDE 521
#define AB_OFF 16672
#define CBA1_OFF (AB_OFF + 8320)
#define QBA0_OFF (AB_OFF + 16640)
#define QBA1_OFF (AB_OFF + 20736)
#define ADB_OFF (AB_OFF + 32768)
#define SMEM_ATTN ((AB_OFF + 34816) * 4)

__device__ __forceinline__ void fill_tileA(float* __restrict__ c_s, float2* __restrict__ qd,
                                           const float* __restrict__ past_c,
                                           int b, int s_base, int kc, int ptid) {
    int sa = s_base + ptid;
    const float* row = (sa < PASTN) ? past_c + ((size_t)b * PASTN + sa) * KVV
                                    : g_cnew + b * KVV;
    #pragma unroll
    for (int kq = 0; kq < 16; kq++) {
        float4 v = *(const float4*)(row + kc * 64 + kq * 4);
        c_s[(kq * 4 + 0) * 130 + ptid] = v.x;
        c_s[(kq * 4 + 1) * 130 + ptid] = v.y;
        c_s[(kq * 4 + 2) * 130 + ptid] = v.z;
        c_s[(kq * 4 + 3) * 130 + ptid] = v.w;
    }
    #pragma unroll
    for (int t = 0; t < 16; t++) {
        int i = ptid + t * 128;
        int k = i >> 5, hh = i & 31;
        float q = g_qabs[((size_t)b * HH + hh) * KVV + kc * 64 + k];
        qd[k * 32 + hh] = make_float2(q, q);
    }
}

__global__ __launch_bounds__(256) void k_attn(const float* __restrict__ past_c) {
    extern __shared__ float sm[];
    __shared__ float m_s[HH];
    float* sc_s = sm;
    int sc = blockIdx.x, b = blockIdx.y;
    int tid = threadIdx.x;
    int w = tid >> 5, lane = tid & 31;
    int S0 = sc * 512;
    bool prod = (w < 4);

    // ===== Phase A: scores [32h][512s] into smem =====
    if (prod) fill_tileA(sm + AB_OFF, (float2*)(sm + QBA0_OFF), past_c, b, S0, 0, tid);
    float2 acc[8][2];
    #pragma unroll
    for (int i = 0; i < 8; i++) { acc[i][0] = make_float2(0.f, 0.f); acc[i][1] = make_float2(0.f, 0.f); }
    __syncthreads();

    int hg = w - 4, sg = lane;
    for (int g = 0; g < 32; g++) {          // g = sub*8 + kc
        if (prod) {
            if (g < 31) {
                int gn = g + 1;
                fill_tileA((gn & 1) ? sm + CBA1_OFF : sm + AB_OFF,
                           (float2*)((gn & 1) ? sm + QBA1_OFF : sm + QBA0_OFF),
                           past_c, b, S0 + (gn >> 3) * 128, gn & 7, tid);
            }
        } else {
            const float*  c_s = (g & 1) ? sm + CBA1_OFF : sm + AB_OFF;
            const float2* qd  = (float2*)((g & 1) ? sm + QBA1_OFF : sm + QBA0_OFF);
            #pragma unroll 2
            for (int k = 0; k < 64; k++) {
                const float4* qp = (const float4*)(qd + k * 32 + hg * 8);
                float4 q0 = qp[0], q1 = qp[1], q2 = qp[2], q3 = qp[3];
                float2 c20 = *(const float2*)&c_s[k * 130 + sg * 2];
                float2 c21 = *(const float2*)&c_s[k * 130 + sg * 2 + 64];
                acc[0][0] = ffma2(make_float2(q0.x, q0.y), c20, acc[0][0]);
                acc[0][1] = ffma2(make_float2(q0.x, q0.y), c21, acc[0][1]);
                acc[1][0] = ffma2(make_float2(q0.z, q0.w), c20, acc[1][0]);
                acc[1][1] = ffma2(make_float2(q0.z, q0.w), c21, acc[1][1]);
                acc[2][0] = ffma2(make_float2(q1.x, q1.y), c20, acc[2][0]);
                acc[2][1] = ffma2(make_float2(q1.x, q1.y), c21, acc[2][1]);
                acc[3][0] = ffma2(make_float2(q1.z, q1.w), c20, acc[3][0]);
                acc[3][1] = ffma2(make_float2(q1.z, q1.w), c21, acc[3][1]);
                acc[4][0] = ffma2(make_float2(q2.x, q2.y), c20, acc[4][0]);
                acc[4][1] = ffma2(make_float2(q2.x, q2.y), c21, acc[4][1]);
                acc[5][0] = ffma2(make_float2(q2.z, q2.w), c20, acc[5][0]);
                acc[5][1] = ffma2(make_float2(q2.z, q2.w), c21, acc[5][1]);
                acc[6][0] = ffma2(make_float2(q3.x, q3.y), c20, acc[6][0]);
                acc[6][1] = ffma2(make_float2(q3.x, q3.y), c21, acc[6][1]);
                acc[7][0] = ffma2(make_float2(q3.z, q3.w), c20, acc[7][0]);
                acc[7][1] = ffma2(make_float2(q3.z, q3.w), c21, acc[7][1]);
            }
            if ((g & 7) == 7) {              // end of sub-tile: dump scores, reset
                int sub = g >> 3;
                #pragma unroll
                for (int i = 0; i < 8; i++) {
                    int h = hg * 8 + i;
                    sc_s[h * SC_STRIDE + sub * 128 + sg * 2 + 0]  = acc[i][0].x;
                    sc_s[h * SC_STRIDE + sub * 128 + sg * 2 + 1]  = acc[i][0].y;
                    sc_s[h * SC_STRIDE + sub * 128 + sg * 2 + 64] = acc[i][1].x;
                    sc_s[h * SC_STRIDE + sub * 128 + sg * 2 + 65] = acc[i][1].y;
                    acc[i][0] = make_float2(0.f, 0.f);
                    acc[i][1] = make_float2(0.f, 0.f);
                }
            }
        }
        __syncthreads();
    }

    // ===== softmax partials over this block's 512 s =====
    #pragma unroll
    for (int r = 0; r < 4; r++) {
        int h = w * 4 + r;
        const float* row = sc_s + h * SC_STRIDE;
        float m = -1e30f;
        #pragma unroll
        for (int t = 0; t < 16; t++) m = fmaxf(m, row[lane + t * 32]);
        #pragma unroll
        for (int o = 16; o; o >>= 1) m = fmaxf(m, __shfl_xor_sync(0xffffffffu, m, o));
        float l = 0.f;
        #pragma unroll
        for (int t = 0; t < 16; t++) l += __expf(row[lane + t * 32] - m);
        #pragma unroll
        for (int o = 16; o; o >>= 1) l += __shfl_xor_sync(0xffffffffu, l, o);
        if (lane == 0) {
            m_s[h] = m;
            g_ml[((sc * BB + b) * HH + h) * 2 + 0] = m;
            g_ml[((sc * BB + b) * HH + h) * 2 + 1] = l;
        }
    }
    __syncthreads();

    // ===== Phase B: o_part = exp(scores-m) @ c_tile (L2-resident re-read) =====
    float* cb = sm + AB_OFF;
    float2* ad = (float2*)(sm + ADB_OFF);
    unsigned sb;
    asm("{.reg .u64 t; cvta.to.shared.u64 t, %1; cvt.u32.u64 %0, t;}" : "=r"(sb) : "l"(sm));
    int hg2 = tid >> 6, ng = tid & 63;
    float2 oacc[8][4];
    #pragma unroll
    for (int i = 0; i < 8; i++)
        #pragma unroll
        for (int j = 0; j < 4; j++) oacc[i][j] = make_float2(0.f, 0.f);

    // issue chunk 0
    {
        #pragma unroll
        for (int t = 0; t < 16; t++) {
            int i = tid + t * 256;
            int s = i >> 7, n4 = i & 127;
            const float* row = (S0 + s < PASTN) ? past_c + ((size_t)b * PASTN + S0 + s) * KVV
                                                : g_cnew + b * KVV;
            cp_async16(sb + (unsigned)(AB_OFF + s * 512 + n4 * 4) * 4u, row + n4 * 4);
        }
        cp_commit();
    }

    for (int ch = 0; ch < 16; ch++) {
        int chS = ch * 32;
        if (ch < 15) {
            int s0n = S0 + chS + 32;
            int base = AB_OFF + ((ch + 1) & 1) * 16384;
            #pragma unroll
            for (int t = 0; t < 16; t++) {
                int i = tid + t * 256;
                int s = i >> 7, n4 = i & 127;
                const float* row = (s0n + s < PASTN) ? past_c + ((size_t)b * PASTN + s0n + s) * KVV
                                                     : g_cnew + b * KVV;
                cp_async16(sb + (unsigned)(base + s * 512 + n4 * 4) * 4u, row + n4 * 4);
            }
            cp_commit();
            asm volatile("cp.async.wait_group 1;");
        } else {
            asm volatile("cp.async.wait_group 0;");
        }
        __syncthreads();
        #pragma unroll
        for (int t = 0; t < 4; t++) {
            int i = tid + t * 256;
            int s2 = i >> 5, hh = i & 31;
            float e = __expf(sc_s[hh * SC_STRIDE + chS + s2] - m_s[hh]);
            ad[s2 * 32 + hh] = make_float2(e, e);
        }
        __syncthreads();
        const float* c_s = cb + (ch & 1) * 16384;
        #pragma unroll 2
        for (int s = 0; s < 32; s++) {
            const float4* ap4 = (const float4*)(ad + s * 32 + hg2 * 8);
            float4 a0 = ap4[0], a1 = ap4[1], a2 = ap4[2], a3 = ap4[3];
            float2 c2[4];
            #pragma unroll
            for (int j = 0; j < 4; j++)
                c2[j] = *(const float2*)&c_s[s * 512 + ng * 2 + j * 128];
            #pragma unroll
            for (int j = 0; j < 4; j++) {
                oacc[0][j] = ffma2(make_float2(a0.x, a0.y), c2[j], oacc[0][j]);
                oacc[1][j] = ffma2(make_float2(a0.z, a0.w), c2[j], oacc[1][j]);
                oacc[2][j] = ffma2(make_float2(a1.x, a1.y), c2[j], oacc[2][j]);
                oacc[3][j] = ffma2(make_float2(a1.z, a1.w), c2[j], oacc[3][j]);
                oacc[4][j] = ffma2(make_float2(a2.x, a2.y), c2[j], oacc[4][j]);
                oacc[5][j] = ffma2(make_float2(a2.z, a2.w), c2[j], oacc[5][j]);
                oacc[6][j] = ffma2(make_float2(a3.x, a3.y), c2[j], oacc[6][j]);
                oacc[7][j] = ffma2(make_float2(a3.z, a3.w), c2[j], oacc[7][j]);
            }
        }
    }
    #pragma unroll
    for (int i = 0; i < 8; i++)
        #pragma unroll
        for (int j = 0; j < 4; j++)
            *(float2*)&g_opart[(((size_t)sc * BB + b) * HH + hg2 * 8 + i) * KVV
                               + ng * 2 + j * 128] = oacc[i][j];
}

// ---------------- K4: combine split-softmax partials -> g_oc ----------------
__global__ void k_combine() {
    int i = blockIdx.x * 256 + threadIdx.x;   // 32768 float4 columns
    int b = i >> 12;
    int h = (i >> 7) & 31;
    float m[NSC];
    float M = -1e30f;
    #pragma unroll
    for (int c = 0; c < NSC; c++) {
        m[c] = g_ml[((c * BB + b) * HH + h) * 2];
        M = fmaxf(M, m[c]);
    }
    float wsum = 0.f;
    float4 acc = make_float4(0.f, 0.f, 0.f, 0.f);
    const float4* p = (const float4*)g_opart;
    #pragma unroll
    for (int c = 0; c < NSC; c++) {
        float wgt = __expf(m[c] - M);
        wsum += wgt * g_ml[((c * BB + b) * HH + h) * 2 + 1];
        float4 t = p[c * 32768 + i];
        acc.x += wgt * t.x; acc.y += wgt * t.y;
        acc.z += wgt * t.z; acc.w += wgt * t.w;
    }
    float inv = 1.f / wsum;
    acc.x *= inv; acc.y *= inv; acc.z *= inv; acc.w *= inv;
    ((float4*)g_oc)[i] = acc;
}

// ---------------- K5: per-head v-up (n-split, atomic) ----------------
__global__ __launch_bounds__(128) void k_vup(const float* __restrict__ wv) {
    __shared__ float2 od[128][8];   // [n_local][b] dup pairs
    int h = blockIdx.x, nc = blockIdx.y;
    int tid = threadIdx.x;
    int jp = tid & 63, g = tid >> 6;
    for (int i = tid; i < 1024; i += 128) {
        int n = i >> 3, b = i & 7;
        float v = g_oc[((size_t)b * HH + h) * KVV + nc * 128 + n];
        od[n][b] = make_float2(v, v);
    }
    __syncthreads();
    float2 acc[BB];
    #pragma unroll
    for (int b = 0; b < BB; b++) acc[b] = make_float2(0.f, 0.f);
    const float* wp = wv + (size_t)(nc * 128 + g * 64) * (HH * HDD) + h * HDD + jp * 2;
    #pragma unroll 8
    for (int n = 0; n < 64; n++) {
        float2 w2 = *(const float2*)(wp + (size_t)n * (HH * HDD));
        #pragma unroll
        for (int b = 0; b < BB; b++)
            acc[b] = ffma2(od[g * 64 + n][b], w2, acc[b]);
    }
    #pragma unroll
    for (int b = 0; b < BB; b++) {
        atomicAdd(&g_ohead[b * DD + h * HDD + jp * 2 + 0], acc[b].x);
        atomicAdd(&g_ohead[b * DD + h * HDD + jp * 2 + 1], acc[b].y);
    }
}

// ---------------- K6: out = out_head @ w_o (m-split over 16, atomic) ----------------
__global__ __launch_bounds__(128) void k_oproj(const float* __restrict__ wo,
                                               float* __restrict__ out) {
    __shared__ float2 ohd[256][8];   // [m_local][b] dup pairs
    int dt = blockIdx.x, mc = blockIdx.y;
    int tid = threadIdx.x;
    for (int i = tid; i < 2048; i += 128) {
        int m = i >> 3, b = i & 7;
        float v = g_ohead[b * DD + mc * 256 + m];
        ohd[m][b] = make_float2(v, v);
    }
    __syncthreads();
    float2 acc[BB];
    #pragma unroll
    for (int b = 0; b < BB; b++) acc[b] = make_float2(0.f, 0.f);
    const float* wp = wo + (size_t)mc * 256 * DD + dt * 256 + tid * 2;
    #pragma unroll 8
    for (int m = 0; m < 256; m++) {
        float2 w2 = *(const float2*)(wp + (size_t)m * DD);
        #pragma unroll
        for (int b = 0; b < BB; b++)
            acc[b] = ffma2(ohd[m][b], w2, acc[b]);
    }
    #pragma unroll
    for (int b = 0; b < BB; b++) {
        atomicAdd(&out[b * DD + dt * 256 + tid * 2 + 0], acc[b].x);
        atomicAdd(&out[b * DD + dt * 256 + tid * 2 + 1], acc[b].y);
    }
}

// ---------------- launch ----------------
extern "C" void kernel_launch(void* const* d_in, const int* in_sizes, int n_in,
                              void* d_out, int out_size) {
    const float* x      = (const float*)d_in[0];
    const float* past_c = (const float*)d_in[1];
    const float* aqk    = (const float*)d_in[2];
    const float* wc     = (const float*)d_in[3];
    const float* wv     = (const float*)d_in[4];
    const float* wo     = (const float*)d_in[5];
    float* out = (float*)d_out;

    cudaFuncSetAttribute(k_attn, cudaFuncAttributeMaxDynamicSharedMemorySize, SMEM_ATTN);

    k_init<<<128, 256>>>(out);
    k_compress<<<32, 256>>>(x, wc);
    k_qabs<<<dim3(NKC, 32), 128>>>(x, aqk);
    k_redq<<<128, 256>>>();
    k_attn<<<dim3(NSC, 8), 256, SMEM_ATTN>>>(past_c);
    k_combine<<<128, 256>>>();
    k_vup<<<dim3(32, 4), 128>>>(wv);
    k_oproj<<<dim3(16, 16), 128>>>(wo, out);
}

// round 6
// speedup vs baseline: 1.1208x; 1.1208x over previous
#include <cuda_runtime.h>

#define BB 8
#define DD 4096
#define HH 32
#define HDD 128
#define KVV 512
#define PASTN 8191
#define TOTALN 8192
#define SCALEF 0.08838834764831845f  // 128^-0.5
#define NSC 16   // s-splits for k_ov
#define NKC 8    // k-splits for qabs

// ---------------- scratch ----------------
__device__ float g_cnew[BB * KVV];
__device__ float g_qabs[BB * HH * KVV];        // zero-init, atomic accumulate
__device__ float g_scores[BB * HH * TOTALN];
__device__ float g_ml2[BB * HH * 2];           // (rowmax, 1/rowsum)
__device__ float g_opart[NSC * BB * HH * KVV];
__device__ float g_oc[BB * HH * KVV];
__device__ float g_ohead[BB * HH * HDD];

// packed dual-fp32 FMA (sm_100+)
__device__ __forceinline__ float2 ffma2(const float2 a, const float2 b, const float2 c) {
    float2 d;
    asm("fma.rn.f32x2 %0, %1, %2, %3;"
        : "=l"(*(unsigned long long*)&d)
        : "l"(*(const unsigned long long*)&a),
          "l"(*(const unsigned long long*)&b),
          "l"(*(const unsigned long long*)&c));
    return d;
}

__device__ __forceinline__ void cp_async16(unsigned s, const void* g) {
    asm volatile("cp.async.cg.shared.global [%0], [%1], 16;" :: "r"(s), "l"(g));
}
__device__ __forceinline__ void cp_commit() {
    asm volatile("cp.async.commit_group;");
}

// ---------------- K0: zero d_out, g_cnew, g_ohead, g_qabs ----------------
__global__ void k_init(float* __restrict__ out) {
    int i = blockIdx.x * 256 + threadIdx.x;       // 131072 threads
    g_qabs[i] = 0.f;
    if (i < BB * DD) { out[i] = 0.f; g_ohead[i] = 0.f; }
    if (i < BB * KVV) g_cnew[i] = 0.f;
}

// ---------------- K1: c_new = x @ w_compress (k-split, atomic) ----------------
__global__ __launch_bounds__(256) void k_compress(const float* __restrict__ x,
                                                  const float* __restrict__ wc) {
    __shared__ float2 xd[128][8];   // [k][b] dup pairs
    int kc = blockIdx.x;            // 32 chunks of 128 k
    int tid = threadIdx.x;
    for (int i = tid; i < 1024; i += 256) {
        int k = i >> 3, b = i & 7;
        float v = x[b * DD + kc * 128 + k];
        xd[k][b] = make_float2(v, v);
    }
    __syncthreads();
    float2 acc[BB];
    #pragma unroll
    for (int b = 0; b < BB; b++) acc[b] = make_float2(0.f, 0.f);
    const float* wp = wc + (size_t)kc * 128 * KVV + tid * 2;
    #pragma unroll 8
    for (int k = 0; k < 128; k++) {
        float2 w2 = *(const float2*)(wp + (size_t)k * KVV);
        #pragma unroll
        for (int b = 0; b < BB; b++)
            acc[b] = ffma2(xd[k][b], w2, acc[b]);
    }
    #pragma unroll
    for (int b = 0; b < BB; b++) {
        atomicAdd(&g_cnew[b * KVV + tid * 2 + 0], acc[b].x);
        atomicAdd(&g_cnew[b * KVV + tid * 2 + 1], acc[b].y);
    }
}

// ---------------- K2: q_abs (scale folded into x), atomic accumulate ----------------
// grid (kc=8, h=32); 128 threads; thread owns n-quad tid*4
__global__ __launch_bounds__(128) void k_qabs(const float* __restrict__ x,
                                              const float* __restrict__ aqk) {
    __shared__ float2 xd[512][8];   // [k][b] dup pairs, pre-scaled (32KB)
    int kc = blockIdx.x;
    int h  = blockIdx.y;
    int tid = threadIdx.x;
    for (int i = tid; i < 4096; i += 128) {
        int k = i >> 3, b = i & 7;
        float v = x[b * DD + kc * 512 + k] * SCALEF;
        xd[k][b] = make_float2(v, v);
    }
    __syncthreads();
    float2 acc[BB][2];
    #pragma unroll
    for (int b = 0; b < BB; b++) {
        acc[b][0] = make_float2(0.f, 0.f);
        acc[b][1] = make_float2(0.f, 0.f);
    }
    const float* ap = aqk + ((size_t)h * DD + (size_t)kc * 512) * KVV + tid * 4;
    #pragma unroll 8
    for (int k = 0; k < 512; k++) {
        float4 a4 = *(const float4*)(ap + (size_t)k * KVV);
        float2 alo = make_float2(a4.x, a4.y);
        float2 ahi = make_float2(a4.z, a4.w);
        #pragma unroll
        for (int b = 0; b < BB; b++) {
            float2 xb = xd[k][b];
            acc[b][0] = ffma2(alo, xb, acc[b][0]);
            acc[b][1] = ffma2(ahi, xb, acc[b][1]);
        }
    }
    #pragma unroll
    for (int b = 0; b < BB; b++) {
        float* dst = &g_qabs[((size_t)b * HH + h) * KVV + tid * 4];
        atomicAdd(dst + 0, acc[b][0].x);
        atomicAdd(dst + 1, acc[b][0].y);
        atomicAdd(dst + 2, acc[b][1].x);
        atomicAdd(dst + 3, acc[b][1].y);
    }
}

// ---------------- K3: scores — stage+transpose producers, 8 compute warps ----------------
// grid (sc=16, b=8); 512 threads: warps 0-7 produce, 8-15 compute.
// smem (floats): cs[2][32k][512s] @0/@16384; stage[512][36] @32768;
//                qd float2[2][32k][32h] @51200/@53248. total 55296 fl = 216KB.
#define CS0 0
#define CS1 16384
#define STG 32768
#define QD0 51200
#define QD1 53248
#define SMEM_SC (55296 * 4)

__device__ __forceinline__ void sc_build(float* __restrict__ sm, unsigned sb,
                                         const float* __restrict__ past_c,
                                         int b, int S0, int hk, int buf, int pid) {
    const int kb = hk * 32;
    #pragma unroll
    for (int j = 0; j < 16; j++) {
        int i = pid + j * 256;
        int s = i >> 3, kq = i & 7;
        const float* row = (S0 + s < PASTN) ? past_c + ((size_t)b * PASTN + S0 + s) * KVV
                                            : g_cnew + b * KVV;
        cp_async16(sb + (unsigned)(STG + s * 36 + kq * 4) * 4u, row + kb + kq * 4);
    }
    cp_commit();
    asm volatile("cp.async.wait_group 0;");
    asm volatile("bar.sync 1, 256;");
    float* cs = sm + (buf ? CS1 : CS0);
    #pragma unroll
    for (int r = 0; r < 2; r++) {
        int s = pid + r * 256;
        const float* st = sm + STG + s * 36;
        #pragma unroll
        for (int q4 = 0; q4 < 8; q4++) {
            float4 v = *(const float4*)(st + q4 * 4);
            cs[(q4 * 4 + 0) * 512 + s] = v.x;
            cs[(q4 * 4 + 1) * 512 + s] = v.y;
            cs[(q4 * 4 + 2) * 512 + s] = v.z;
            cs[(q4 * 4 + 3) * 512 + s] = v.w;
        }
    }
    float2* qd = (float2*)(sm + (buf ? QD1 : QD0));
    #pragma unroll
    for (int t = 0; t < 4; t++) {
        int idx = pid + t * 256;
        int kl = idx >> 5, h = idx & 31;
        float q = g_qabs[((size_t)b * HH + h) * KVV + kb + kl];
        qd[kl * 32 + h] = make_float2(q, q);
    }
}

__global__ __launch_bounds__(512) void k_scores(const float* __restrict__ past_c) {
    extern __shared__ float sm[];
    int sc = blockIdx.x, b = blockIdx.y;
    int tid = threadIdx.x;
    int S0 = sc * 512;
    unsigned sb;
    asm("{.reg .u64 t; cvta.to.shared.u64 t, %1; cvt.u32.u64 %0, t;}" : "=r"(sb) : "l"(sm));
    bool prod = (tid < 256);

    if (prod) sc_build(sm, sb, past_c, b, S0, 0, 0, tid);

    float2 acc[16][2];
    #pragma unroll
    for (int i = 0; i < 16; i++) { acc[i][0] = make_float2(0.f, 0.f); acc[i][1] = make_float2(0.f, 0.f); }
    __syncthreads();

    int cid = tid - 256;
    int w2 = cid >> 5, lane = cid & 31;
    int hgrp = w2 >> 2, sgrp = w2 & 3;       // 16 h, 128 s per warp
    int sp = sgrp * 128 + lane * 2;

    for (int hk = 0; hk < 16; hk++) {
        if (prod) {
            if (hk < 15) sc_build(sm, sb, past_c, b, S0, hk + 1, (hk + 1) & 1, tid);
        } else {
            const float*  cs = sm + ((hk & 1) ? CS1 : CS0);
            const float2* qd = (const float2*)(sm + ((hk & 1) ? QD1 : QD0));
            #pragma unroll 2
            for (int kl = 0; kl < 32; kl++) {
                const float4* qp = (const float4*)(qd + kl * 32 + hgrp * 16);
                float4 qq[8];
                #pragma unroll
                for (int j = 0; j < 8; j++) qq[j] = qp[j];
                float2 c0 = *(const float2*)&cs[kl * 512 + sp];
                float2 c1 = *(const float2*)&cs[kl * 512 + sp + 64];
                #pragma unroll
                for (int j = 0; j < 8; j++) {
                    float2 qa = make_float2(qq[j].x, qq[j].y);
                    float2 qb = make_float2(qq[j].z, qq[j].w);
                    acc[2 * j][0]     = ffma2(qa, c0, acc[2 * j][0]);
                    acc[2 * j][1]     = ffma2(qa, c1, acc[2 * j][1]);
                    acc[2 * j + 1][0] = ffma2(qb, c0, acc[2 * j + 1][0]);
                    acc[2 * j + 1][1] = ffma2(qb, c1, acc[2 * j + 1][1]);
                }
            }
        }
        __syncthreads();
    }
    if (!prod) {
        #pragma unroll
        for (int i = 0; i < 16; i++) {
            int h = hgrp * 16 + i;
            *(float2*)&g_scores[((size_t)b * HH + h) * TOTALN + S0 + sp]      = acc[i][0];
            *(float2*)&g_scores[((size_t)b * HH + h) * TOTALN + S0 + sp + 64] = acc[i][1];
        }
    }
}

// ---------------- K4: row stats (m, 1/l) per (b,h); read-only over scores ----------------
__global__ __launch_bounds__(256) void k_mrow() {
    int bh = blockIdx.x;
    int tid = threadIdx.x;
    int w = tid >> 5, lane = tid & 31;
    const float* row = g_scores + (size_t)bh * TOTALN;
    float4 v[8];
    #pragma unroll
    for (int i = 0; i < 8; i++) v[i] = ((const float4*)row)[tid * 8 + i];
    float m = -1e30f;
    #pragma unroll
    for (int i = 0; i < 8; i++)
        m = fmaxf(m, fmaxf(fmaxf(v[i].x, v[i].y), fmaxf(v[i].z, v[i].w)));
    #pragma unroll
    for (int o = 16; o; o >>= 1) m = fmaxf(m, __shfl_xor_sync(0xffffffffu, m, o));
    __shared__ float redm[8], reds[8];
    if (lane == 0) redm[w] = m;
    __syncthreads();
    m = redm[0];
    #pragma unroll
    for (int i = 1; i < 8; i++) m = fmaxf(m, redm[i]);
    float s = 0.f;
    #pragma unroll
    for (int i = 0; i < 8; i++)
        s += __expf(v[i].x - m) + __expf(v[i].y - m) + __expf(v[i].z - m) + __expf(v[i].w - m);
    #pragma unroll
    for (int o = 16; o; o >>= 1) s += __shfl_xor_sync(0xffffffffu, s, o);
    if (lane == 0) reds[w] = s;
    __syncthreads();
    if (tid == 0) {
        s = reds[0] + reds[1] + reds[2] + reds[3] + reds[4] + reds[5] + reds[6] + reds[7];
        g_ml2[bh * 2 + 0] = m;
        g_ml2[bh * 2 + 1] = 1.f / s;
    }
}

// ---------------- K5: o_c partials = softmax(scores) @ c_full (cp.async pipelined) ----------------
// grid (sc=16, b=8); 256 threads; 16 chunks of 32 s; exp+1/l applied inline
__device__ __forceinline__ void ov_issue(unsigned sb, const float* __restrict__ past_c,
                                         int b, int s0, int bufbase, int tid) {
    #pragma unroll
    for (int t = 0; t < 16; t++) {
        int i = tid + t * 256;
        int s = i >> 7, n4 = i & 127;
        const float* row = (s0 + s < PASTN) ? past_c + ((size_t)b * PASTN + s0 + s) * KVV
                                            : g_cnew + b * KVV;
        cp_async16(sb + (unsigned)(bufbase + s * 512 + n4 * 4) * 4u, row + n4 * 4);
    }
    cp_commit();
}

__global__ __launch_bounds__(256) void k_ov(const float* __restrict__ past_c) {
    extern __shared__ float sm[];
    __shared__ float msh[HH], ilsh[HH];
    float*  cb = sm;                          // 2 * 16384 floats
    float2* ad = (float2*)(sm + 2 * 16384);   // 1024 float2
    int sc = blockIdx.x, b = blockIdx.y;
    int tid = threadIdx.x;
    unsigned sb;
    asm("{.reg .u64 t; cvta.to.shared.u64 t, %1; cvt.u32.u64 %0, t;}" : "=r"(sb) : "l"(sm));
    int S0 = sc * 512;
    int hg = tid >> 6, ng = tid & 63;
    if (tid < HH) {
        msh[tid]  = g_ml2[(b * HH + tid) * 2 + 0];
        ilsh[tid] = g_ml2[(b * HH + tid) * 2 + 1];
    }
    float2 acc[8][4];
    #pragma unroll
    for (int i = 0; i < 8; i++)
        #pragma unroll
        for (int j = 0; j < 4; j++) acc[i][j] = make_float2(0.f, 0.f);

    ov_issue(sb, past_c, b, S0, 0, tid);

    for (int ch = 0; ch < 16; ch++) {
        int s0 = S0 + ch * 32;
        if (ch < 15) {
            ov_issue(sb, past_c, b, s0 + 32, ((ch + 1) & 1) * 16384, tid);
            asm volatile("cp.async.wait_group 1;");
        } else {
            asm volatile("cp.async.wait_group 0;");
        }
        __syncthreads();
        #pragma unroll
        for (int t = 0; t < 4; t++) {
            int i = tid + t * 256;
            int s2 = i >> 5, hh = i & 31;
            float e = __expf(g_scores[((size_t)b * HH + hh) * TOTALN + s0 + s2] - msh[hh]) * ilsh[hh];
            ad[s2 * 32 + hh] = make_float2(e, e);
        }
        __syncthreads();
        const float* c_s = cb + (ch & 1) * 16384;
        #pragma unroll 2
        for (int s = 0; s < 32; s++) {
            const float4* ap4 = (const float4*)(ad + s * 32 + hg * 8);
            float4 a0 = ap4[0], a1 = ap4[1], a2 = ap4[2], a3 = ap4[3];
            float2 c2[4];
            #pragma unroll
            for (int j = 0; j < 4; j++)
                c2[j] = *(const float2*)&c_s[s * 512 + ng * 2 + j * 128];
            #pragma unroll
            for (int j = 0; j < 4; j++) {
                acc[0][j] = ffma2(make_float2(a0.x, a0.y), c2[j], acc[0][j]);
                acc[1][j] = ffma2(make_float2(a0.z, a0.w), c2[j], acc[1][j]);
                acc[2][j] = ffma2(make_float2(a1.x, a1.y), c2[j], acc[2][j]);
                acc[3][j] = ffma2(make_float2(a1.z, a1.w), c2[j], acc[3][j]);
                acc[4][j] = ffma2(make_float2(a2.x, a2.y), c2[j], acc[4][j]);
                acc[5][j] = ffma2(make_float2(a2.z, a2.w), c2[j], acc[5][j]);
                acc[6][j] = ffma2(make_float2(a3.x, a3.y), c2[j], acc[6][j]);
                acc[7][j] = ffma2(make_float2(a3.z, a3.w), c2[j], acc[7][j]);
            }
        }
    }
    #pragma unroll
    for (int i = 0; i < 8; i++)
        #pragma unroll
        for (int j = 0; j < 4; j++)
            *(float2*)&g_opart[(((size_t)sc * BB + b) * HH + hg * 8 + i) * KVV
                               + ng * 2 + j * 128] = acc[i][j];
}

// reduce NSC s-partials -> g_oc
__global__ void k_redo() {
    int i = blockIdx.x * 256 + threadIdx.x;
    const float4* p = (const float4*)g_opart;
    float4 s = make_float4(0.f, 0.f, 0.f, 0.f);
    #pragma unroll
    for (int c = 0; c < NSC; c++) {
        float4 t = p[c * 32768 + i];
        s.x += t.x; s.y += t.y; s.z += t.z; s.w += t.w;
    }
    ((float4*)g_oc)[i] = s;
}

// ---------------- K6: per-head v-up (n-split, atomic) ----------------
__global__ __launch_bounds__(128) void k_vup(const float* __restrict__ wv) {
    __shared__ float2 od[128][8];   // [n_local][b] dup pairs
    int h = blockIdx.x, nc = blockIdx.y;
    int tid = threadIdx.x;
    int jp = tid & 63, g = tid >> 6;
    for (int i = tid; i < 1024; i += 128) {
        int n = i >> 3, b = i & 7;
        float v = g_oc[((size_t)b * HH + h) * KVV + nc * 128 + n];
        od[n][b] = make_float2(v, v);
    }
    __syncthreads();
    float2 acc[BB];
    #pragma unroll
    for (int b = 0; b < BB; b++) acc[b] = make_float2(0.f, 0.f);
    const float* wp = wv + (size_t)(nc * 128 + g * 64) * (HH * HDD) + h * HDD + jp * 2;
    #pragma unroll 8
    for (int n = 0; n < 64; n++) {
        float2 w2 = *(const float2*)(wp + (size_t)n * (HH * HDD));
        #pragma unroll
        for (int b = 0; b < BB; b++)
            acc[b] = ffma2(od[g * 64 + n][b], w2, acc[b]);
    }
    #pragma unroll
    for (int b = 0; b < BB; b++) {
        atomicAdd(&g_ohead[b * DD + h * HDD + jp * 2 + 0], acc[b].x);
        atomicAdd(&g_ohead[b * DD + h * HDD + jp * 2 + 1], acc[b].y);
    }
}

// ---------------- K7: out = out_head @ w_o (m-split over 16, atomic) ----------------
__global__ __launch_bounds__(128) void k_oproj(const float* __restrict__ wo,
                                               float* __restrict__ out) {
    __shared__ float2 ohd[256][8];   // [m_local][b] dup pairs
    int dt = blockIdx.x, mc = blockIdx.y;
    int tid = threadIdx.x;
    for (int i = tid; i < 2048; i += 128) {
        int m = i >> 3, b = i & 7;
        float v = g_ohead[b * DD + mc * 256 + m];
        ohd[m][b] = make_float2(v, v);
    }
    __syncthreads();
    float2 acc[BB];
    #pragma unroll
    for (int b = 0; b < BB; b++) acc[b] = make_float2(0.f, 0.f);
    const float* wp = wo + (size_t)mc * 256 * DD + dt * 256 + tid * 2;
    #pragma unroll 8
    for (int m = 0; m < 256; m++) {
        float2 w2 = *(const float2*)(wp + (size_t)m * DD);
        #pragma unroll
        for (int b = 0; b < BB; b++)
            acc[b] = ffma2(ohd[m][b], w2, acc[b]);
    }
    #pragma unroll
    for (int b = 0; b < BB; b++) {
        atomicAdd(&out[b * DD + dt * 256 + tid * 2 + 0], acc[b].x);
        atomicAdd(&out[b * DD + dt * 256 + tid * 2 + 1], acc[b].y);
    }
}

// ---------------- launch ----------------
extern "C" void kernel_launch(void* const* d_in, const int* in_sizes, int n_in,
                              void* d_out, int out_size) {
    const float* x      = (const float*)d_in[0];
    const float* past_c = (const float*)d_in[1];
    const float* aqk    = (const float*)d_in[2];
    const float* wc     = (const float*)d_in[3];
    const float* wv     = (const float*)d_in[4];
    const float* wo     = (const float*)d_in[5];
    float* out = (float*)d_out;

    const int SMEM_K5 = (2 * 16384 + 1024 * 2) * 4;   // 139264
    cudaFuncSetAttribute(k_scores, cudaFuncAttributeMaxDynamicSharedMemorySize, SMEM_SC);
    cudaFuncSetAttribute(k_ov,     cudaFuncAttributeMaxDynamicSharedMemorySize, SMEM_K5);

    k_init<<<512, 256>>>(out);                          // idx 0
    k_compress<<<32, 256>>>(x, wc);                     // idx 1
    k_qabs<<<dim3(NKC, 32), 128>>>(x, aqk);             // idx 2
    k_scores<<<dim3(16, 8), 512, SMEM_SC>>>(past_c);    // idx 3  <- profiled
    k_mrow<<<256, 256>>>();                             // idx 4
    k_ov<<<dim3(NSC, 8), 256, SMEM_K5>>>(past_c);       // idx 5
    k_redo<<<128, 256>>>();                             // idx 6
    k_vup<<<dim3(32, 4), 128>>>(wv);                    // idx 7
    k_oproj<<<dim3(16, 16), 128>>>(wo, out);            // idx 8
}

// round 7
// speedup vs baseline: 1.3254x; 1.1825x over previous
#include <cuda_runtime.h>

#define BB 8
#define DD 4096
#define HH 32
#define HDD 128
#define KVV 512
#define PASTN 8191
#define TOTALN 8192
#define SCALEF 0.08838834764831845f  // 128^-0.5
#define NSC 16   // s-splits for k_ov
#define NKC 16   // k-splits for qabs

// ---------------- scratch ----------------
__device__ float g_cnew[BB * KVV];
__device__ float g_qabs[BB * HH * KVV];        // zero-init, atomic accumulate
__device__ float g_scores[BB * HH * TOTALN];
__device__ float g_ml2[BB * HH * 2];           // (rowmax, 1/rowsum)
__device__ float g_opart[NSC * BB * HH * KVV];
__device__ float g_oc[BB * HH * KVV];
__device__ float g_ohead[BB * HH * HDD];

// packed dual-fp32 FMA (sm_100+)
__device__ __forceinline__ float2 ffma2(const float2 a, const float2 b, const float2 c) {
    float2 d;
    asm("fma.rn.f32x2 %0, %1, %2, %3;"
        : "=l"(*(unsigned long long*)&d)
        : "l"(*(const unsigned long long*)&a),
          "l"(*(const unsigned long long*)&b),
          "l"(*(const unsigned long long*)&c));
    return d;
}

__device__ __forceinline__ void cp_async16(unsigned s, const void* g) {
    asm volatile("cp.async.cg.shared.global [%0], [%1], 16;" :: "r"(s), "l"(g));
}
__device__ __forceinline__ void cp_commit() {
    asm volatile("cp.async.commit_group;");
}

// ---------------- K0: zero d_out, g_cnew, g_ohead, g_qabs ----------------
__global__ void k_init(float* __restrict__ out) {
    int i = blockIdx.x * 256 + threadIdx.x;       // 131072 threads
    g_qabs[i] = 0.f;
    if (i < BB * DD) { out[i] = 0.f; g_ohead[i] = 0.f; }
    if (i < BB * KVV) g_cnew[i] = 0.f;
}

// ---------------- K1: c_new = x @ w_compress (k-split, atomic) ----------------
__global__ __launch_bounds__(256) void k_compress(const float* __restrict__ x,
                                                  const float* __restrict__ wc) {
    __shared__ float2 xd[128][8];   // [k][b] dup pairs
    int kc = blockIdx.x;            // 32 chunks of 128 k
    int tid = threadIdx.x;
    for (int i = tid; i < 1024; i += 256) {
        int k = i >> 3, b = i & 7;
        float v = x[b * DD + kc * 128 + k];
        xd[k][b] = make_float2(v, v);
    }
    __syncthreads();
    float2 acc[BB];
    #pragma unroll
    for (int b = 0; b < BB; b++) acc[b] = make_float2(0.f, 0.f);
    const float* wp = wc + (size_t)kc * 128 * KVV + tid * 2;
    #pragma unroll 8
    for (int k = 0; k < 128; k++) {
        float2 w2 = *(const float2*)(wp + (size_t)k * KVV);
        #pragma unroll
        for (int b = 0; b < BB; b++)
            acc[b] = ffma2(xd[k][b], w2, acc[b]);
    }
    #pragma unroll
    for (int b = 0; b < BB; b++) {
        atomicAdd(&g_cnew[b * KVV + tid * 2 + 0], acc[b].x);
        atomicAdd(&g_cnew[b * KVV + tid * 2 + 1], acc[b].y);
    }
}

// ---------------- K2: q_abs (scale folded into x), atomic accumulate ----------------
// grid (kc=16, h=32); 128 threads; thread owns n-quad tid*4
__global__ __launch_bounds__(128) void k_qabs(const float* __restrict__ x,
                                              const float* __restrict__ aqk) {
    __shared__ float2 xd[256][8];   // [k][b] dup pairs, pre-scaled (16KB)
    int kc = blockIdx.x;
    int h  = blockIdx.y;
    int tid = threadIdx.x;
    for (int i = tid; i < 2048; i += 128) {
        int k = i >> 3, b = i & 7;
        float v = x[b * DD + kc * 256 + k] * SCALEF;
        xd[k][b] = make_float2(v, v);
    }
    __syncthreads();
    float2 acc[BB][2];
    #pragma unroll
    for (int b = 0; b < BB; b++) {
        acc[b][0] = make_float2(0.f, 0.f);
        acc[b][1] = make_float2(0.f, 0.f);
    }
    const float* ap = aqk + ((size_t)h * DD + (size_t)kc * 256) * KVV + tid * 4;
    #pragma unroll 8
    for (int k = 0; k < 256; k++) {
        float4 a4 = *(const float4*)(ap + (size_t)k * KVV);
        float2 alo = make_float2(a4.x, a4.y);
        float2 ahi = make_float2(a4.z, a4.w);
        #pragma unroll
        for (int b = 0; b < BB; b++) {
            float2 xb = xd[k][b];
            acc[b][0] = ffma2(alo, xb, acc[b][0]);
            acc[b][1] = ffma2(ahi, xb, acc[b][1]);
        }
    }
    #pragma unroll
    for (int b = 0; b < BB; b++) {
        float* dst = &g_qabs[((size_t)b * HH + h) * KVV + tid * 4];
        atomicAdd(dst + 0, acc[b][0].x);
        atomicAdd(dst + 1, acc[b][0].y);
        atomicAdd(dst + 2, acc[b][1].x);
        atomicAdd(dst + 3, acc[b][1].y);
    }
}

// ---------------- K3: scores — all 16 warps compute, split-k + transpose ----------------
// grid (sc=16, b=8); 512 threads; warp = (hgrp[4] x sgrp[2] x kgrp[2]).
// smem (floats): cs[2][32k][512s] @0/@16384; stage[512][36] @32768;
//                qd fl2[2][32k][34] @51200/@53376. total 55552 fl = 217KB.
#define CS0 0
#define CS1 16384
#define STGO 32768
#define QD0 51200
#define QD1 53376
#define SMEM_SC (55552 * 4)

__global__ __launch_bounds__(512) void k_scores(const float* __restrict__ past_c) {
    extern __shared__ float sm[];
    int sc = blockIdx.x, b = blockIdx.y;
    int tid = threadIdx.x;
    int S0 = sc * 512;
    unsigned sb;
    asm("{.reg .u64 t; cvta.to.shared.u64 t, %1; cvt.u32.u64 %0, t;}" : "=r"(sb) : "l"(sm));
    int w = tid >> 5, lane = tid & 31;
    int hgrp = w >> 2, sgrp = (w >> 1) & 1, kgrp = w & 1;

    // prologue: issue chunk 0 into stage
    #pragma unroll
    for (int j = 0; j < 8; j++) {
        int i = tid + j * 512;
        int s = i >> 3, kq = i & 7;
        const float* row = (S0 + s < PASTN) ? past_c + ((size_t)b * PASTN + S0 + s) * KVV
                                            : g_cnew + b * KVV;
        cp_async16(sb + (unsigned)(STGO + s * 36 + kq * 4) * 4u, row + kq * 4);
    }
    cp_commit();

    float2 acc[8][4];
    #pragma unroll
    for (int i = 0; i < 8; i++)
        #pragma unroll
        for (int j = 0; j < 4; j++) acc[i][j] = make_float2(0.f, 0.f);

    for (int hk = 0; hk < 16; hk++) {
        int kb = hk * 32;
        asm volatile("cp.async.wait_group 0;");
        __syncthreads();                       // stage ready; prev compute done
        // transpose stage[s][36] -> cs[hk&1][k][512]
        {
            const float* st = sm + STGO + tid * 36;
            float* cs = sm + ((hk & 1) ? CS1 : CS0);
            #pragma unroll
            for (int q = 0; q < 8; q++) {
                float4 v = *(const float4*)(st + q * 4);
                cs[(q * 4 + 0) * 512 + tid] = v.x;
                cs[(q * 4 + 1) * 512 + tid] = v.y;
                cs[(q * 4 + 2) * 512 + tid] = v.z;
                cs[(q * 4 + 3) * 512 + tid] = v.w;
            }
        }
        // q chunk: warp w handles h = w, w+16; lane = k  (coalesced LDG)
        {
            float2* qd = (float2*)(sm + ((hk & 1) ? QD1 : QD0));
            #pragma unroll
            for (int t = 0; t < 2; t++) {
                int h = w + t * 16;
                float q = g_qabs[((size_t)b * HH + h) * KVV + kb + lane];
                qd[lane * 34 + h] = make_float2(q, q);
            }
        }
        __syncthreads();                       // transpose reads done; cs/qd visible
        if (hk < 15) {                         // stage now free -> issue next chunk
            int kb2 = kb + 32;
            #pragma unroll
            for (int j = 0; j < 8; j++) {
                int i = tid + j * 512;
                int s = i >> 3, kq = i & 7;
                const float* row = (S0 + s < PASTN) ? past_c + ((size_t)b * PASTN + S0 + s) * KVV
                                                    : g_cnew + b * KVV;
                cp_async16(sb + (unsigned)(STGO + s * 36 + kq * 4) * 4u, row + kb2 + kq * 4);
            }
            cp_commit();
        }
        // compute (overlaps cp.async flight)
        {
            const float*  cs = sm + ((hk & 1) ? CS1 : CS0);
            const float2* qd = (const float2*)(sm + ((hk & 1) ? QD1 : QD0));
            int sp = sgrp * 256 + lane * 2;
            #pragma unroll 2
            for (int k = kgrp * 16; k < kgrp * 16 + 16; k++) {
                const float4* qp = (const float4*)(qd + k * 34 + hgrp * 8);
                float4 q0 = qp[0], q1 = qp[1], q2 = qp[2], q3 = qp[3];
                float2 c2[4];
                #pragma unroll
                for (int j = 0; j < 4; j++)
                    c2[j] = *(const float2*)&cs[k * 512 + sp + j * 64];
                #pragma unroll
                for (int j = 0; j < 4; j++) {
                    acc[0][j] = ffma2(make_float2(q0.x, q0.y), c2[j], acc[0][j]);
                    acc[1][j] = ffma2(make_float2(q0.z, q0.w), c2[j], acc[1][j]);
                    acc[2][j] = ffma2(make_float2(q1.x, q1.y), c2[j], acc[2][j]);
                    acc[3][j] = ffma2(make_float2(q1.z, q1.w), c2[j], acc[3][j]);
                    acc[4][j] = ffma2(make_float2(q2.x, q2.y), c2[j], acc[4][j]);
                    acc[5][j] = ffma2(make_float2(q2.z, q2.w), c2[j], acc[5][j]);
                    acc[6][j] = ffma2(make_float2(q3.x, q3.y), c2[j], acc[6][j]);
                    acc[7][j] = ffma2(make_float2(q3.z, q3.w), c2[j], acc[7][j]);
                }
            }
        }
    }
    // cross-kgrp reduction through smem (reuse cs0 region), then store
    __syncthreads();
    float2* red = (float2*)sm;
    int wid8 = hgrp * 2 + sgrp;
    if (kgrp == 1) {
        #pragma unroll
        for (int i = 0; i < 8; i++)
            #pragma unroll
            for (int j = 0; j < 4; j++)
                red[((wid8 * 32 + lane) * 8 + i) * 4 + j] = acc[i][j];
    }
    __syncthreads();
    if (kgrp == 0) {
        #pragma unroll
        for (int i = 0; i < 8; i++)
            #pragma unroll
            for (int j = 0; j < 4; j++) {
                float2 p = red[((wid8 * 32 + lane) * 8 + i) * 4 + j];
                acc[i][j].x += p.x; acc[i][j].y += p.y;
                *(float2*)&g_scores[((size_t)b * HH + hgrp * 8 + i) * TOTALN
                                    + S0 + sgrp * 256 + lane * 2 + j * 64] = acc[i][j];
            }
    }
}

// ---------------- K4: row stats (m, 1/l) per (b,h) ----------------
__global__ __launch_bounds__(256) void k_mrow() {
    int bh = blockIdx.x;
    int tid = threadIdx.x;
    int w = tid >> 5, lane = tid & 31;
    const float* row = g_scores + (size_t)bh * TOTALN;
    float4 v[8];
    #pragma unroll
    for (int i = 0; i < 8; i++) v[i] = ((const float4*)row)[tid * 8 + i];
    float m = -1e30f;
    #pragma unroll
    for (int i = 0; i < 8; i++)
        m = fmaxf(m, fmaxf(fmaxf(v[i].x, v[i].y), fmaxf(v[i].z, v[i].w)));
    #pragma unroll
    for (int o = 16; o; o >>= 1) m = fmaxf(m, __shfl_xor_sync(0xffffffffu, m, o));
    __shared__ float redm[8], reds[8];
    if (lane == 0) redm[w] = m;
    __syncthreads();
    m = redm[0];
    #pragma unroll
    for (int i = 1; i < 8; i++) m = fmaxf(m, redm[i]);
    float s = 0.f;
    #pragma unroll
    for (int i = 0; i < 8; i++)
        s += __expf(v[i].x - m) + __expf(v[i].y - m) + __expf(v[i].z - m) + __expf(v[i].w - m);
    #pragma unroll
    for (int o = 16; o; o >>= 1) s += __shfl_xor_sync(0xffffffffu, s, o);
    if (lane == 0) reds[w] = s;
    __syncthreads();
    if (tid == 0) {
        s = reds[0] + reds[1] + reds[2] + reds[3] + reds[4] + reds[5] + reds[6] + reds[7];
        g_ml2[bh * 2 + 0] = m;
        g_ml2[bh * 2 + 1] = 1.f / s;
    }
}

// ---------------- K5: o_c partials — all 16 warps compute, split-s ----------------
// grid (sc=16, b=8); 512 threads; warp = (hgrp[4] x ngrp[2] x sgrp[2]).
// smem: cb[2][32s][512n] @0 (32768 fl); ad fl2[32s][34] @32768 (2176 fl).
#define ADOFF 32768
#define SMEM_OV ((32768 + 2176) * 4)

__global__ __launch_bounds__(512) void k_ov(const float* __restrict__ past_c) {
    extern __shared__ float sm[];
    __shared__ float msh[HH], ilsh[HH];
    int sc = blockIdx.x, b = blockIdx.y;
    int tid = threadIdx.x;
    unsigned sb;
    asm("{.reg .u64 t; cvta.to.shared.u64 t, %1; cvt.u32.u64 %0, t;}" : "=r"(sb) : "l"(sm));
    int S0 = sc * 512;
    int w = tid >> 5, lane = tid & 31;
    int hgrp = w >> 2, ngrp = (w >> 1) & 1, sgrp = w & 1;
    if (tid < HH) {
        msh[tid]  = g_ml2[(b * HH + tid) * 2 + 0];
        ilsh[tid] = g_ml2[(b * HH + tid) * 2 + 1];
    }
    float2 acc[8][4];
    #pragma unroll
    for (int i = 0; i < 8; i++)
        #pragma unroll
        for (int j = 0; j < 4; j++) acc[i][j] = make_float2(0.f, 0.f);

    // prologue: issue chunk 0
    #pragma unroll
    for (int t = 0; t < 8; t++) {
        int i = tid + t * 512;
        int s = i >> 7, n4 = i & 127;
        const float* row = (S0 + s < PASTN) ? past_c + ((size_t)b * PASTN + S0 + s) * KVV
                                            : g_cnew + b * KVV;
        cp_async16(sb + (unsigned)(s * 512 + n4 * 4) * 4u, row + n4 * 4);
    }
    cp_commit();

    float2* ad = (float2*)(sm + ADOFF);
    for (int ch = 0; ch < 16; ch++) {
        int s0 = S0 + ch * 32;
        asm volatile("cp.async.wait_group 0;");
        __syncthreads();                   // chunk ch visible; compute(ch-1) done
        // ad fill: warp w handles h = w, w+16; lane = s  (coalesced LDG)
        #pragma unroll
        for (int t = 0; t < 2; t++) {
            int h = w + t * 16;
            float e = __expf(g_scores[((size_t)b * HH + h) * TOTALN + s0 + lane] - msh[h]) * ilsh[h];
            ad[lane * 34 + h] = make_float2(e, e);
        }
        if (ch < 15) {                     // issue next into buffer (ch+1)&1 (safe: last reader synced)
            int s0n = s0 + 32;
            int base = ((ch + 1) & 1) * 16384;
            #pragma unroll
            for (int t = 0; t < 8; t++) {
                int i = tid + t * 512;
                int s = i >> 7, n4 = i & 127;
                const float* row = (s0n + s < PASTN) ? past_c + ((size_t)b * PASTN + s0n + s) * KVV
                                                     : g_cnew + b * KVV;
                cp_async16(sb + (unsigned)(base + s * 512 + n4 * 4) * 4u, row + n4 * 4);
            }
            cp_commit();
        }
        __syncthreads();                   // ad visible
        const float* c_s = sm + (ch & 1) * 16384;
        #pragma unroll 2
        for (int s = sgrp * 16; s < sgrp * 16 + 16; s++) {
            const float4* ap4 = (const float4*)(ad + s * 34 + hgrp * 8);
            float4 a0 = ap4[0], a1 = ap4[1], a2 = ap4[2], a3 = ap4[3];
            float2 c2[4];
            #pragma unroll
            for (int j = 0; j < 4; j++)
                c2[j] = *(const float2*)&c_s[s * 512 + (ngrp * 128 + j * 32 + lane) * 2];
            #pragma unroll
            for (int j = 0; j < 4; j++) {
                acc[0][j] = ffma2(make_float2(a0.x, a0.y), c2[j], acc[0][j]);
                acc[1][j] = ffma2(make_float2(a0.z, a0.w), c2[j], acc[1][j]);
                acc[2][j] = ffma2(make_float2(a1.x, a1.y), c2[j], acc[2][j]);
                acc[3][j] = ffma2(make_float2(a1.z, a1.w), c2[j], acc[3][j]);
                acc[4][j] = ffma2(make_float2(a2.x, a2.y), c2[j], acc[4][j]);
                acc[5][j] = ffma2(make_float2(a2.z, a2.w), c2[j], acc[5][j]);
                acc[6][j] = ffma2(make_float2(a3.x, a3.y), c2[j], acc[6][j]);
                acc[7][j] = ffma2(make_float2(a3.z, a3.w), c2[j], acc[7][j]);
            }
        }
    }
    // cross-sgrp reduction (reuse cb[0] region), then store
    __syncthreads();
    float2* red = (float2*)sm;
    int wid8 = hgrp * 2 + ngrp;
    if (sgrp == 1) {
        #pragma unroll
        for (int i = 0; i < 8; i++)
            #pragma unroll
            for (int j = 0; j < 4; j++)
                red[((wid8 * 32 + lane) * 8 + i) * 4 + j] = acc[i][j];
    }
    __syncthreads();
    if (sgrp == 0) {
        #pragma unroll
        for (int i = 0; i < 8; i++)
            #pragma unroll
            for (int j = 0; j < 4; j++) {
                float2 p = red[((wid8 * 32 + lane) * 8 + i) * 4 + j];
                acc[i][j].x += p.x; acc[i][j].y += p.y;
                *(float2*)&g_opart[(((size_t)sc * BB + b) * HH + hgrp * 8 + i) * KVV
                                   + (ngrp * 128 + j * 32 + lane) * 2] = acc[i][j];
            }
    }
}

// reduce NSC s-partials -> g_oc
__global__ void k_redo() {
    int i = blockIdx.x * 256 + threadIdx.x;
    const float4* p = (const float4*)g_opart;
    float4 s = make_float4(0.f, 0.f, 0.f, 0.f);
    #pragma unroll
    for (int c = 0; c < NSC; c++) {
        float4 t = p[c * 32768 + i];
        s.x += t.x; s.y += t.y; s.z += t.z; s.w += t.w;
    }
    ((float4*)g_oc)[i] = s;
}

// ---------------- K6: per-head v-up (n-split, atomic) ----------------
__global__ __launch_bounds__(128) void k_vup(const float* __restrict__ wv) {
    __shared__ float2 od[128][8];   // [n_local][b] dup pairs
    int h = blockIdx.x, nc = blockIdx.y;
    int tid = threadIdx.x;
    int jp = tid & 63, g = tid >> 6;
    for (int i = tid; i < 1024; i += 128) {
        int n = i >> 3, b = i & 7;
        float v = g_oc[((size_t)b * HH + h) * KVV + nc * 128 + n];
        od[n][b] = make_float2(v, v);
    }
    __syncthreads();
    float2 acc[BB];
    #pragma unroll
    for (int b = 0; b < BB; b++) acc[b] = make_float2(0.f, 0.f);
    const float* wp = wv + (size_t)(nc * 128 + g * 64) * (HH * HDD) + h * HDD + jp * 2;
    #pragma unroll 8
    for (int n = 0; n < 64; n++) {
        float2 w2 = *(const float2*)(wp + (size_t)n * (HH * HDD));
        #pragma unroll
        for (int b = 0; b < BB; b++)
            acc[b] = ffma2(od[g * 64 + n][b], w2, acc[b]);
    }
    #pragma unroll
    for (int b = 0; b < BB; b++) {
        atomicAdd(&g_ohead[b * DD + h * HDD + jp * 2 + 0], acc[b].x);
        atomicAdd(&g_ohead[b * DD + h * HDD + jp * 2 + 1], acc[b].y);
    }
}

// ---------------- K7: out = out_head @ w_o (m-split over 16, atomic) ----------------
__global__ __launch_bounds__(128) void k_oproj(const float* __restrict__ wo,
                                               float* __restrict__ out) {
    __shared__ float2 ohd[256][8];   // [m_local][b] dup pairs
    int dt = blockIdx.x, mc = blockIdx.y;
    int tid = threadIdx.x;
    for (int i = tid; i < 2048; i += 128) {
        int m = i >> 3, b = i & 7;
        float v = g_ohead[b * DD + mc * 256 + m];
        ohd[m][b] = make_float2(v, v);
    }
    __syncthreads();
    float2 acc[BB];
    #pragma unroll
    for (int b = 0; b < BB; b++) acc[b] = make_float2(0.f, 0.f);
    const float* wp = wo + (size_t)mc * 256 * DD + dt * 256 + tid * 2;
    #pragma unroll 8
    for (int m = 0; m < 256; m++) {
        float2 w2 = *(const float2*)(wp + (size_t)m * DD);
        #pragma unroll
        for (int b = 0; b < BB; b++)
            acc[b] = ffma2(ohd[m][b], w2, acc[b]);
    }
    #pragma unroll
    for (int b = 0; b < BB; b++) {
        atomicAdd(&out[b * DD + dt * 256 + tid * 2 + 0], acc[b].x);
        atomicAdd(&out[b * DD + dt * 256 + tid * 2 + 1], acc[b].y);
    }
}

// ---------------- launch ----------------
extern "C" void kernel_launch(void* const* d_in, const int* in_sizes, int n_in,
                              void* d_out, int out_size) {
    const float* x      = (const float*)d_in[0];
    const float* past_c = (const float*)d_in[1];
    const float* aqk    = (const float*)d_in[2];
    const float* wc     = (const float*)d_in[3];
    const float* wv     = (const float*)d_in[4];
    const float* wo     = (const float*)d_in[5];
    float* out = (float*)d_out;

    cudaFuncSetAttribute(k_scores, cudaFuncAttributeMaxDynamicSharedMemorySize, SMEM_SC);
    cudaFuncSetAttribute(k_ov,     cudaFuncAttributeMaxDynamicSharedMemorySize, SMEM_OV);

    k_init<<<512, 256>>>(out);                          // idx 0
    k_compress<<<32, 256>>>(x, wc);                     // idx 1
    k_qabs<<<dim3(NKC, 32), 128>>>(x, aqk);             // idx 2
    k_scores<<<dim3(16, 8), 512, SMEM_SC>>>(past_c);    // idx 3  <- profiled
    k_mrow<<<256, 256>>>();                             // idx 4
    k_ov<<<dim3(NSC, 8), 512, SMEM_OV>>>(past_c);       // idx 5
    k_redo<<<128, 256>>>();                             // idx 6
    k_vup<<<dim3(32, 4), 128>>>(wv);                    // idx 7
    k_oproj<<<dim3(16, 16), 128>>>(wo, out);            // idx 8
}